// round 10
// baseline (speedup 1.0000x reference)
#include <cuda_runtime.h>
#include <cstdint>

#define NN 4096
#define DD 512
#define FF 512
#define HH 4
#define KK 1024
#define ALPHA 0.3f
#define L2E 1.4426950408889634f
#define ST 40        // padded smem row stride (floats)

// ---- scratch (device globals; no allocation allowed) ----
__device__ float g_A[NN * KK];          // tf32, k-permuted, [m][k]
__device__ float g_BT[HH * FF * KK];    // tf32, k-permuted, [h][f][k]
__device__ float g_bias2[HH * FF];
__device__ float g_featsT[(size_t)HH * FF * NN];  // tf32, m-permuted, [h][f][m]
__device__ float g_s[HH * NN];
__device__ float g_t[HH * NN];
__device__ float g_rmax[HH * NN];
__device__ float g_invz[HH * NN];
__device__ float g_wu[HH * DD];
__device__ float g_wv[HH * DD];
__device__ float g_bu[HH];
__device__ float g_bv[HH];
__device__ float g_hpmax[HH];
__device__ float g_hmmin[HH];

// ================= helpers =================
__device__ __host__ __forceinline__ int kperm(int r) {   // within-8 permutation
    return r < 4 ? 2 * r : 2 * r - 7;
}
__device__ __forceinline__ float warp_sum(float x) {
#pragma unroll
    for (int o = 16; o > 0; o >>= 1) x += __shfl_xor_sync(0xffffffffu, x, o);
    return x;
}
__device__ __forceinline__ uint32_t cvt_tf32(float x) {
    uint32_t r; asm("cvt.rna.tf32.f32 %0, %1;" : "=r"(r) : "f"(x)); return r;
}
__device__ __forceinline__ float tf32r(float x) {
    return __uint_as_float(cvt_tf32(x));
}
__device__ __forceinline__ float fex2(float y) {
    float r; asm("ex2.approx.ftz.f32 %0, %1;" : "=f"(r) : "f"(y)); return r;
}
__device__ __forceinline__ uint32_t smem_u32(const void* p) {
    uint32_t a;
    asm("{ .reg .u64 t; cvta.to.shared.u64 t, %1; cvt.u32.u64 %0, t; }"
        : "=r"(a) : "l"(p));
    return a;
}
__device__ __forceinline__ void cpasync16(uint32_t dst, const void* src) {
    asm volatile("cp.async.cg.shared.global [%0], [%1], 16;" :: "r"(dst), "l"(src));
}
__device__ __forceinline__ void cp_commit() {
    asm volatile("cp.async.commit_group;" ::: "memory");
}
template <int N>
__device__ __forceinline__ void cp_wait() {
    asm volatile("cp.async.wait_group %0;" :: "n"(N) : "memory");
}
__device__ __forceinline__ void mma1688(float* c, uint32_t a0, uint32_t a1,
                                        uint32_t a2, uint32_t a3,
                                        uint32_t b0, uint32_t b1) {
    asm volatile(
        "mma.sync.aligned.m16n8k8.row.col.f32.tf32.tf32.f32 "
        "{%0,%1,%2,%3}, {%4,%5,%6,%7}, {%8,%9}, {%0,%1,%2,%3};"
        : "+f"(c[0]), "+f"(c[1]), "+f"(c[2]), "+f"(c[3])
        : "r"(a0), "r"(a1), "r"(a2), "r"(a3), "r"(b0), "r"(b1));
}

// ================= fused setup kernel =================
// blocks [0, 2048)     : build_A (k-permuted)
// blocks [2048, 4096)  : build_BT (transpose, k-permuted)
// blocks [4096, 4104)  : bias2
// blocks [4104, 4360)  : wuwv
// block  4360          : bubv
#define SETUP_BLOCKS 4361

__global__ __launch_bounds__(256) void setup_kernel(
    const float* __restrict__ nodes, const float* __restrict__ edges,
    const float* __restrict__ labels, const float* __restrict__ W,
    const float* __restrict__ We, const float* __restrict__ b,
    const float* __restrict__ be, const float* __restrict__ u,
    const float* __restrict__ v)
{
    __shared__ float tile[32][33];
    int bx = blockIdx.x;
    int tid = threadIdx.x;
    if (bx < 2048) {
        int i = bx * 256 + tid;           // float4 index over NN*DD/4
        int m = i >> 7, dq = i & 127;
        float4 a = ((const float4*)nodes)[i];
        float4 x = ((const float4*)edges)[i];
        float4 y = ((const float4*)labels)[i];
        float* row = g_A + (size_t)m * KK;
        float av[4] = {a.x, a.y, a.z, a.w};
        float cv[4] = {x.x + y.x, x.y + y.y, x.z + y.z, x.w + y.w};
#pragma unroll
        for (int j = 0; j < 4; j++) {
            int k1 = dq * 4 + j;
            row[(k1 & ~7) | kperm(k1 & 7)] = tf32r(av[j]);
            int k2 = DD + dq * 4 + j;
            row[(k2 & ~7) | kperm(k2 & 7)] = tf32r(cv[j]);
        }
    } else if (bx < 4096) {
        int jb = bx - 2048;               // HH * 32 * 16
        int h = jb >> 9;
        int r = jb & 511;
        int k0 = (r >> 4) * 32, f0 = (r & 15) * 32;
        int tx = tid & 31, ty0 = tid >> 5;
#pragma unroll
        for (int j = 0; j < 4; j++) {
            int ty = ty0 * 4 + j;
            int k = k0 + ty;
            float vv = (k < DD) ? W[((size_t)h * DD + k) * FF + f0 + tx]
                                : We[(size_t)(k - DD) * FF + f0 + tx];
            tile[ty][tx] = vv;
        }
        __syncthreads();
#pragma unroll
        for (int j = 0; j < 4; j++) {
            int ty = ty0 * 4 + j;
            int c = k0 + tx;
            g_BT[((size_t)h * FF + f0 + ty) * KK + ((c & ~7) | kperm(c & 7))]
                = tf32r(tile[tx][ty]);
        }
    } else if (bx < 4104) {
        int i = (bx - 4096) * 256 + tid;  // HH*FF = 2048
        int f = i & (FF - 1);
        g_bias2[i] = b[i] + be[f];
    } else if (bx < 4360) {
        int w = (bx - 4104) * 8 + (tid >> 5);   // HH*DD warps
        int lane = tid & 31;
        int h = w / DD, d = w % DD;
        const float4* Wr = (const float4*)(W + ((long)h * DD + d) * FF);
        const float4* up = (const float4*)(u + (long)h * FF);
        const float4* vp = (const float4*)(v + (long)h * FF);
        float su = 0.f, sv = 0.f;
        for (int i = lane; i < FF / 4; i += 32) {
            float4 w4 = Wr[i], u4 = up[i], v4 = vp[i];
            su += w4.x * u4.x + w4.y * u4.y + w4.z * u4.z + w4.w * u4.w;
            sv += w4.x * v4.x + w4.y * v4.y + w4.z * v4.z + w4.w * v4.w;
        }
        su = warp_sum(su); sv = warp_sum(sv);
        if (lane == 0) { g_wu[h * DD + d] = su; g_wv[h * DD + d] = sv; }
    } else {
        if (tid < 128) {
            int h = tid >> 5;
            int lane = tid & 31;
            float su = 0.f, sv = 0.f;
            for (int i = lane; i < FF; i += 32) {
                float bb = b[h * FF + i];
                su += bb * u[h * FF + i];
                sv += bb * v[h * FF + i];
            }
            su = warp_sum(su); sv = warp_sum(sv);
            if (lane == 0) { g_bu[h] = su; g_bv[h] = sv; }
        }
    }
}

// ================= rank-1 precomputation =================
__global__ __launch_bounds__(256) void st_kernel(const float* __restrict__ nodes) {
    int w = blockIdx.x * 8 + (threadIdx.x >> 5);
    int lane = threadIdx.x & 31;
    int h = w >> 12;
    int n = w & (NN - 1);
    const float4* nr = (const float4*)(nodes + (long)n * DD);
    const float4* wu = (const float4*)(g_wu + (long)h * DD);
    const float4* wv = (const float4*)(g_wv + (long)h * DD);
    float ss = 0.f, tt = 0.f;
    for (int i = lane; i < DD / 4; i += 32) {
        float4 x = nr[i], a = wu[i], c = wv[i];
        ss += x.x * a.x + x.y * a.y + x.z * a.z + x.w * a.w;
        tt += x.x * c.x + x.y * c.y + x.z * c.z + x.w * c.w;
    }
    ss = warp_sum(ss); tt = warp_sum(tt);
    if (lane == 0) {
        g_s[h * NN + n] = ss + g_bu[h];
        g_t[h * NN + n] = tt + g_bv[h];
    }
}

__global__ void minmax_kernel() {
    int h = blockIdx.x;
    int tid = threadIdx.x;
    __shared__ float smx[256], smn[256];
    float mx = -1e30f, mn = 1e30f;
    for (int m = tid; m < NN; m += 256) {
        float t = g_t[h * NN + m];
        float hp = t >= 0.f ? t : ALPHA * t;
        float hm = t <= 0.f ? t : ALPHA * t;
        mx = fmaxf(mx, hp);
        mn = fminf(mn, hm);
    }
    smx[tid] = mx; smn[tid] = mn;
    __syncthreads();
    for (int sft = 128; sft > 0; sft >>= 1) {
        if (tid < sft) {
            smx[tid] = fmaxf(smx[tid], smx[tid + sft]);
            smn[tid] = fminf(smn[tid], smn[tid + sft]);
        }
        __syncthreads();
    }
    if (tid == 0) { g_hpmax[h] = smx[0]; g_hmmin[h] = smn[0]; }
}

__global__ __launch_bounds__(256) void z_kernel() {
    int w = blockIdx.x * 8 + (threadIdx.x >> 5);
    int lane = threadIdx.x & 31;
    int h = w >> 12, n = w & (NN - 1);
    float s = g_s[h * NN + n];
    float rmax = s > 0.f ? s * g_hpmax[h] : (s < 0.f ? s * g_hmmin[h] : 0.f);
    const float* tp = g_t + (long)h * NN;
    float z = 0.f;
    for (int m = lane; m < NN; m += 32) {
        float sc = s * tp[m];
        sc = sc >= 0.f ? sc : ALPHA * sc;
        z += fex2(fmaxf((sc - rmax) * L2E, -126.f));
    }
    z = warp_sum(z);
    if (lane == 0) {
        g_rmax[h * NN + n] = rmax;
        g_invz[h * NN + n] = 1.f / z;
    }
}

// ================= feats GEMM (mma.sync tf32, 2-stage, LDS.64 frags) =================
#define F_AS (128 * ST)            // 5120 floats
#define F_STG (2 * F_AS)           // 10240 floats
#define F_SMEM (2 * F_STG * 4)     // 81920 bytes

__global__ __launch_bounds__(256) void feats_gemm() {
    extern __shared__ float sm[];
    int tid = threadIdx.x, wid = tid >> 5, lane = tid & 31;
    int g = lane >> 2, tg = lane & 3;
    int h = blockIdx.z;
    int m0 = blockIdx.y * 128, f0 = blockIdx.x * 128;
    const float* Bp = g_BT + (size_t)h * FF * KK;
    int warp_m = wid & 3, warp_n = wid >> 2;

    float acc[2][8][4];
#pragma unroll
    for (int a = 0; a < 2; a++)
#pragma unroll
        for (int bq = 0; bq < 8; bq++)
#pragma unroll
            for (int c = 0; c < 4; c++) acc[a][bq][c] = 0.f;

    int prow = tid & 127, pseg = tid >> 7;

    auto prod = [&](int c, int s) {
        float* As = sm + s * F_STG;
        float* Bs = As + F_AS;
        int k0 = c * 32;
        const float* asrc = g_A + (size_t)(m0 + prow) * KK + k0 + pseg * 16;
        const float* bsrc = Bp + (size_t)(f0 + prow) * KK + k0 + pseg * 16;
        uint32_t ad = smem_u32(As + prow * ST + pseg * 16);
        uint32_t bd = smem_u32(Bs + prow * ST + pseg * 16);
#pragma unroll
        for (int j = 0; j < 4; j++) {
            cpasync16(ad + j * 16, asrc + j * 4);
            cpasync16(bd + j * 16, bsrc + j * 4);
        }
    };
    auto domma = [&](int s) {
        float* As = sm + s * F_STG;
        float* Bs = As + F_AS;
#pragma unroll
        for (int ks = 0; ks < 4; ks++) {
            float2 alo[2], ahi[2];
#pragma unroll
            for (int mt = 0; mt < 2; mt++) {
                int base = warp_m * 32 + mt * 16;
                alo[mt] = *(float2*)&As[(base + g) * ST + ks * 8 + 2 * tg];
                ahi[mt] = *(float2*)&As[(base + 8 + g) * ST + ks * 8 + 2 * tg];
            }
#pragma unroll
            for (int nt = 0; nt < 8; nt++) {
                int fc = warp_n * 64 + nt * 8 + g;
                float2 b2 = *(float2*)&Bs[fc * ST + ks * 8 + 2 * tg];
                uint32_t b0 = __float_as_uint(b2.x), b1 = __float_as_uint(b2.y);
#pragma unroll
                for (int mt = 0; mt < 2; mt++)
                    mma1688(acc[mt][nt],
                            __float_as_uint(alo[mt].x), __float_as_uint(ahi[mt].x),
                            __float_as_uint(alo[mt].y), __float_as_uint(ahi[mt].y),
                            b0, b1);
            }
        }
    };

    const int NIT = KK / 32;   // 32
    prod(0, 0); cp_commit();
    for (int i = 0; i < NIT; i++) {
        int s = i & 1;
        if (i + 1 < NIT) { prod(i + 1, s ^ 1); cp_commit(); cp_wait<1>(); }
        else cp_wait<0>();
        __syncthreads();
        domma(s);
        __syncthreads();
    }

    // epilogue: write featsT m-PERMUTED so attn's B matches attn's A layout
    float* dst = g_featsT + (size_t)h * FF * NN;
    int pg = kperm(g);
#pragma unroll
    for (int mt = 0; mt < 2; mt++) {
#pragma unroll
        for (int nt = 0; nt < 8; nt++) {
            int base = m0 + warp_m * 32 + mt * 16;
            int col = f0 + warp_n * 64 + nt * 8 + tg * 2;
            float b0v = g_bias2[h * FF + col];
            float b1v = g_bias2[h * FF + col + 1];
            dst[(size_t)col * NN + base + pg]           = tf32r(acc[mt][nt][0] + b0v);
            dst[(size_t)(col + 1) * NN + base + pg]     = tf32r(acc[mt][nt][1] + b1v);
            dst[(size_t)col * NN + base + 8 + pg]       = tf32r(acc[mt][nt][2] + b0v);
            dst[(size_t)(col + 1) * NN + base + 8 + pg] = tf32r(acc[mt][nt][3] + b1v);
        }
    }
}

// ================= fused attention GEMM (mma.sync tf32, 2-stage) =================
// CTA 64n x 128f, grid (4, 64) = 256 CTAs -> 2/SM. 8 warps 2m x 4n, warp 32n x 32f.
// w = 2^( s_n*t_m * (>=0 ? L2E : 0.3*L2E) + C_n ), C_n = log2(invz_n) - rmax_n*L2E
#define A_CONST 512                 // s_sm[256] + c_sm[256]
#define A_AS (64 * ST)              // 2560
#define A_STG (A_AS + 128 * ST)     // 7680
#define A_SMEM ((A_CONST + 2 * A_STG) * 4)   // 63488 bytes

__global__ __launch_bounds__(256) void attn_gemm(float* __restrict__ out) {
    extern __shared__ float sm[];
    float* s_sm = sm;              // [4h][64]
    float* c_sm = sm + 256;        // [4h][64]
    int tid = threadIdx.x, wid = tid >> 5, lane = tid & 31;
    int g = lane >> 2, tg = lane & 3;
    int n0 = blockIdx.y * 64, f0 = blockIdx.x * 128;
    int warp_m = wid & 1, warp_n = wid >> 1;

    {
        int hh = tid >> 6, nl = tid & 63;
        float iz = g_invz[hh * NN + n0 + nl];
        float rm = g_rmax[hh * NN + n0 + nl];
        s_sm[tid] = g_s[hh * NN + n0 + nl];
        c_sm[tid] = __log2f(iz) - rm * L2E;
    }

    float acc[2][4][4];
#pragma unroll
    for (int a = 0; a < 2; a++)
#pragma unroll
        for (int bq = 0; bq < 4; bq++)
#pragma unroll
            for (int c = 0; c < 4; c++) acc[a][bq][c] = 0.f;

    int nloc = tid & 63, kq = tid >> 6;       // weight gen: 8 k's each
    int prow = tid & 127, pseg = tid >> 7;    // B copy

    auto prod = [&](int c, int s) {
        float* As = sm + A_CONST + s * A_STG;
        float* Bs = As + A_AS;
        int h = c >> 7;
        int m0 = (c & 127) << 5;
        float sv = s_sm[h * 64 + nloc];
        float cn = c_sm[h * 64 + nloc];
        const float4* tp = (const float4*)(g_t + h * NN + m0 + kq * 8);
        float w[8];
#pragma unroll
        for (int q = 0; q < 2; q++) {
            float4 t4 = __ldg(tp + q);
            float tv[4] = {t4.x, t4.y, t4.z, t4.w};
#pragma unroll
            for (int r = 0; r < 4; r++) {
                float sc = sv * tv[r];
                float mult = sc >= 0.f ? L2E : (ALPHA * L2E);
                float y = fmaxf(fmaf(sc, mult, cn), -126.f);
                w[q * 4 + r] = tf32r(fex2(y));
            }
        }
        float* d = As + nloc * ST + kq * 8;
        // k-permuted store: positions hold k = 0,4,1,5,2,6,3,7
        *(float4*)d       = make_float4(w[0], w[4], w[1], w[5]);
        *(float4*)(d + 4) = make_float4(w[2], w[6], w[3], w[7]);
        const float* bsrc = g_featsT + (size_t)h * FF * NN
                          + (size_t)(f0 + prow) * NN + m0 + pseg * 16;
        uint32_t bd = smem_u32(Bs + prow * ST + pseg * 16);
#pragma unroll
        for (int j = 0; j < 4; j++) cpasync16(bd + j * 16, bsrc + j * 4);
    };
    auto domma = [&](int s) {
        float* As = sm + A_CONST + s * A_STG;
        float* Bs = As + A_AS;
#pragma unroll
        for (int ks = 0; ks < 4; ks++) {
            float2 alo[2], ahi[2];
#pragma unroll
            for (int mt = 0; mt < 2; mt++) {
                int base = warp_m * 32 + mt * 16;
                alo[mt] = *(float2*)&As[(base + g) * ST + ks * 8 + 2 * tg];
                ahi[mt] = *(float2*)&As[(base + 8 + g) * ST + ks * 8 + 2 * tg];
            }
#pragma unroll
            for (int nt = 0; nt < 4; nt++) {
                int fc = warp_n * 32 + nt * 8 + g;
                float2 b2 = *(float2*)&Bs[fc * ST + ks * 8 + 2 * tg];
                uint32_t b0 = __float_as_uint(b2.x), b1 = __float_as_uint(b2.y);
#pragma unroll
                for (int mt = 0; mt < 2; mt++)
                    mma1688(acc[mt][nt],
                            __float_as_uint(alo[mt].x), __float_as_uint(ahi[mt].x),
                            __float_as_uint(alo[mt].y), __float_as_uint(ahi[mt].y),
                            b0, b1);
            }
        }
    };

    const int NIT = HH * (NN / 32);   // 512
    __syncthreads();                  // s_sm/c_sm ready
    prod(0, 0); cp_commit();
    for (int i = 0; i < NIT; i++) {
        int s = i & 1;
        if (i + 1 < NIT) { prod(i + 1, s ^ 1); cp_commit(); cp_wait<1>(); }
        else cp_wait<0>();
        __syncthreads();
        domma(s);
        __syncthreads();
    }

#pragma unroll
    for (int mt = 0; mt < 2; mt++) {
#pragma unroll
        for (int nt = 0; nt < 4; nt++) {
            int row = n0 + warp_m * 32 + mt * 16 + g;
            int col = f0 + warp_n * 32 + nt * 8 + tg * 2;
            float2 v0, v1;
            v0.x = fmaxf(0.25f * acc[mt][nt][0], 0.f);
            v0.y = fmaxf(0.25f * acc[mt][nt][1], 0.f);
            v1.x = fmaxf(0.25f * acc[mt][nt][2], 0.f);
            v1.y = fmaxf(0.25f * acc[mt][nt][3], 0.f);
            *(float2*)(out + (size_t)row * FF + col) = v0;
            *(float2*)(out + (size_t)(row + 8) * FF + col) = v1;
        }
    }
}

// ================= launch =================
extern "C" void kernel_launch(void* const* d_in, const int* in_sizes, int n_in,
                              void* d_out, int out_size)
{
    const float* nodes  = (const float*)d_in[0];
    const float* edges  = (const float*)d_in[1];
    const float* labels = (const float*)d_in[2];
    const float* We     = (const float*)d_in[3];
    const float* be     = (const float*)d_in[4];
    const float* Wm     = (const float*)d_in[5];
    const float* b      = (const float*)d_in[6];
    const float* u      = (const float*)d_in[7];
    const float* v      = (const float*)d_in[8];
    float* out = (float*)d_out;

    static bool attr_done = false;
    if (!attr_done) {
        cudaFuncSetAttribute(feats_gemm, cudaFuncAttributeMaxDynamicSharedMemorySize, F_SMEM);
        cudaFuncSetAttribute(attn_gemm, cudaFuncAttributeMaxDynamicSharedMemorySize, A_SMEM);
        cudaFuncSetAttribute(feats_gemm, cudaFuncAttributePreferredSharedMemoryCarveout, 100);
        cudaFuncSetAttribute(attn_gemm, cudaFuncAttributePreferredSharedMemoryCarveout, 100);
        attr_done = true;
    }

    setup_kernel<<<SETUP_BLOCKS, 256>>>(nodes, edges, labels, Wm, We, b, be, u, v);
    st_kernel<<<HH * NN / 8, 256>>>(nodes);
    minmax_kernel<<<HH, 256>>>();
    feats_gemm<<<dim3(FF / 128, NN / 128, HH), 256, F_SMEM>>>();  // capture slot 4
    z_kernel<<<HH * NN / 8, 256>>>();
    attn_gemm<<<dim3(FF / 128, NN / 64), 256, A_SMEM>>>(out);
}

// round 13
// speedup vs baseline: 1.4151x; 1.4151x over previous
#include <cuda_runtime.h>
#include <cstdint>

#define NN 4096
#define DD 512
#define FF 512
#define HH 4
#define KK 1024
#define ALPHA 0.3f
#define L2E 1.4426950408889634f
#define ST 36        // padded smem row stride (floats)

// ---- scratch (device globals; no allocation allowed) ----
__device__ float g_A[NN * KK];          // tf32-rounded [nodes | edges+labels], [m][k]
__device__ float g_BT[HH * FF * KK];    // tf32-rounded [h][f][k] = [W^T | We^T]
__device__ float g_bias2[HH * FF];
__device__ float g_featsT[(size_t)HH * FF * NN];  // [h][f][m], tf32-rounded
__device__ float g_s[HH * NN];
__device__ float g_t[HH * NN];
__device__ float g_rmax[HH * NN];
__device__ float g_invz[HH * NN];
__device__ float g_wu[HH * DD];
__device__ float g_wv[HH * DD];
__device__ float g_bu[HH];
__device__ float g_bv[HH];
__device__ float g_hpmax[HH];
__device__ float g_hmmin[HH];

// ================= helpers =================
__device__ __forceinline__ float warp_sum(float x) {
#pragma unroll
    for (int o = 16; o > 0; o >>= 1) x += __shfl_xor_sync(0xffffffffu, x, o);
    return x;
}
__device__ __forceinline__ uint32_t cvt_tf32(float x) {
    uint32_t r; asm("cvt.rna.tf32.f32 %0, %1;" : "=r"(r) : "f"(x)); return r;
}
__device__ __forceinline__ float tf32r(float x) {
    return __uint_as_float(cvt_tf32(x));
}
__device__ __forceinline__ float fex2(float y) {
    float r; asm("ex2.approx.ftz.f32 %0, %1;" : "=f"(r) : "f"(y)); return r;
}
__device__ __forceinline__ uint32_t smem_u32(const void* p) {
    uint32_t a;
    asm("{ .reg .u64 t; cvta.to.shared.u64 t, %1; cvt.u32.u64 %0, t; }"
        : "=r"(a) : "l"(p));
    return a;
}
__device__ __forceinline__ void cpasync16(uint32_t dst, const void* src) {
    asm volatile("cp.async.cg.shared.global [%0], [%1], 16;" :: "r"(dst), "l"(src));
}
__device__ __forceinline__ void cp_commit() {
    asm volatile("cp.async.commit_group;" ::: "memory");
}
template <int N>
__device__ __forceinline__ void cp_wait() {
    asm volatile("cp.async.wait_group %0;" :: "n"(N) : "memory");
}
__device__ __forceinline__ void mma1688(float* c, const uint32_t* a, uint32_t b0, uint32_t b1) {
    asm volatile(
        "mma.sync.aligned.m16n8k8.row.col.f32.tf32.tf32.f32 "
        "{%0,%1,%2,%3}, {%4,%5,%6,%7}, {%8,%9}, {%0,%1,%2,%3};"
        : "+f"(c[0]), "+f"(c[1]), "+f"(c[2]), "+f"(c[3])
        : "r"(a[0]), "r"(a[1]), "r"(a[2]), "r"(a[3]), "r"(b0), "r"(b1));
}

// ================= fused setup kernel =================
// blocks [0, 2048)     : build_A
// blocks [2048, 4096)  : build_BT (tiled transpose)
// blocks [4096, 4104)  : bias2
// blocks [4104, 4360)  : wuwv
// block  4360          : bubv
#define SETUP_BLOCKS 4361

__global__ __launch_bounds__(256) void setup_kernel(
    const float* __restrict__ nodes, const float* __restrict__ edges,
    const float* __restrict__ labels, const float* __restrict__ W,
    const float* __restrict__ We, const float* __restrict__ b,
    const float* __restrict__ be, const float* __restrict__ u,
    const float* __restrict__ v)
{
    __shared__ float tile[32][33];
    int bx = blockIdx.x;
    int tid = threadIdx.x;
    if (bx < 2048) {
        int i = bx * 256 + tid;           // float4 index over NN*DD/4
        int m = i >> 7, dq = i & 127;
        float4 a = ((const float4*)nodes)[i];
        float4 x = ((const float4*)edges)[i];
        float4 y = ((const float4*)labels)[i];
        float* h0 = g_A + (size_t)m * KK + dq * 4;
        float av[4] = {a.x, a.y, a.z, a.w};
        float cv[4] = {x.x + y.x, x.y + y.y, x.z + y.z, x.w + y.w};
#pragma unroll
        for (int j = 0; j < 4; j++) {
            h0[j] = tf32r(av[j]);
            h0[DD + j] = tf32r(cv[j]);
        }
    } else if (bx < 4096) {
        int jb = bx - 2048;
        int h = jb >> 9;
        int r = jb & 511;
        int k0 = (r >> 4) * 32, f0 = (r & 15) * 32;
        int tx = tid & 31, ty0 = tid >> 5;
#pragma unroll
        for (int j = 0; j < 4; j++) {
            int ty = ty0 * 4 + j;
            int k = k0 + ty;
            float vv = (k < DD) ? W[((size_t)h * DD + k) * FF + f0 + tx]
                                : We[(size_t)(k - DD) * FF + f0 + tx];
            tile[ty][tx] = vv;
        }
        __syncthreads();
#pragma unroll
        for (int j = 0; j < 4; j++) {
            int ty = ty0 * 4 + j;
            g_BT[((size_t)h * FF + f0 + ty) * KK + k0 + tx] = tf32r(tile[tx][ty]);
        }
    } else if (bx < 4104) {
        int i = (bx - 4096) * 256 + tid;
        int f = i & (FF - 1);
        g_bias2[i] = b[i] + be[f];
    } else if (bx < 4360) {
        int w = (bx - 4104) * 8 + (tid >> 5);
        int lane = tid & 31;
        int h = w / DD, d = w % DD;
        const float4* Wr = (const float4*)(W + ((long)h * DD + d) * FF);
        const float4* up = (const float4*)(u + (long)h * FF);
        const float4* vp = (const float4*)(v + (long)h * FF);
        float su = 0.f, sv = 0.f;
        for (int i = lane; i < FF / 4; i += 32) {
            float4 w4 = Wr[i], u4 = up[i], v4 = vp[i];
            su += w4.x * u4.x + w4.y * u4.y + w4.z * u4.z + w4.w * u4.w;
            sv += w4.x * v4.x + w4.y * v4.y + w4.z * v4.z + w4.w * v4.w;
        }
        su = warp_sum(su); sv = warp_sum(sv);
        if (lane == 0) { g_wu[h * DD + d] = su; g_wv[h * DD + d] = sv; }
    } else {
        if (tid < 128) {
            int h = tid >> 5;
            int lane = tid & 31;
            float su = 0.f, sv = 0.f;
            for (int i = lane; i < FF; i += 32) {
                float bb = b[h * FF + i];
                su += bb * u[h * FF + i];
                sv += bb * v[h * FF + i];
            }
            su = warp_sum(su); sv = warp_sum(sv);
            if (lane == 0) { g_bu[h] = su; g_bv[h] = sv; }
        }
    }
}

// ================= rank-1 precomputation =================
__global__ __launch_bounds__(256) void st_kernel(const float* __restrict__ nodes) {
    int w = blockIdx.x * 8 + (threadIdx.x >> 5);
    int lane = threadIdx.x & 31;
    int h = w >> 12;
    int n = w & (NN - 1);
    const float4* nr = (const float4*)(nodes + (long)n * DD);
    const float4* wu = (const float4*)(g_wu + (long)h * DD);
    const float4* wv = (const float4*)(g_wv + (long)h * DD);
    float ss = 0.f, tt = 0.f;
    for (int i = lane; i < DD / 4; i += 32) {
        float4 x = nr[i], a = wu[i], c = wv[i];
        ss += x.x * a.x + x.y * a.y + x.z * a.z + x.w * a.w;
        tt += x.x * c.x + x.y * c.y + x.z * c.z + x.w * c.w;
    }
    ss = warp_sum(ss); tt = warp_sum(tt);
    if (lane == 0) {
        g_s[h * NN + n] = ss + g_bu[h];
        g_t[h * NN + n] = tt + g_bv[h];
    }
}

__global__ void minmax_kernel() {
    int h = blockIdx.x;
    int tid = threadIdx.x;
    __shared__ float smx[256], smn[256];
    float mx = -1e30f, mn = 1e30f;
    for (int m = tid; m < NN; m += 256) {
        float t = g_t[h * NN + m];
        float hp = t >= 0.f ? t : ALPHA * t;
        float hm = t <= 0.f ? t : ALPHA * t;
        mx = fmaxf(mx, hp);
        mn = fminf(mn, hm);
    }
    smx[tid] = mx; smn[tid] = mn;
    __syncthreads();
    for (int sft = 128; sft > 0; sft >>= 1) {
        if (tid < sft) {
            smx[tid] = fmaxf(smx[tid], smx[tid + sft]);
            smn[tid] = fminf(smn[tid], smn[tid + sft]);
        }
        __syncthreads();
    }
    if (tid == 0) { g_hpmax[h] = smx[0]; g_hmmin[h] = smn[0]; }
}

__global__ __launch_bounds__(256) void z_kernel() {
    int w = blockIdx.x * 8 + (threadIdx.x >> 5);
    int lane = threadIdx.x & 31;
    int h = w >> 12, n = w & (NN - 1);
    float s = g_s[h * NN + n];
    float rmax = s > 0.f ? s * g_hpmax[h] : (s < 0.f ? s * g_hmmin[h] : 0.f);
    const float* tp = g_t + (long)h * NN;
    float z = 0.f;
    for (int m = lane; m < NN; m += 32) {
        float sc = s * tp[m];
        sc = sc >= 0.f ? sc : ALPHA * sc;
        z += fex2(fmaxf((sc - rmax) * L2E, -126.f));
    }
    z = warp_sum(z);
    if (lane == 0) {
        g_rmax[h * NN + n] = rmax;
        g_invz[h * NN + n] = 1.f / z;
    }
}

// ================= feats GEMM (mma.sync tf32, 2-stage, 1 barrier/iter) ==========
#define F_AS (128 * ST)            // 4608 floats
#define F_STG (2 * F_AS)           // 9216 floats
#define F_SMEM (2 * F_STG * 4)     // 73728 bytes -> 2 CTAs/SM

__global__ __launch_bounds__(256) void feats_gemm() {
    extern __shared__ float sm[];
    int tid = threadIdx.x, wid = tid >> 5, lane = tid & 31;
    int g = lane >> 2, tg = lane & 3;
    int h = blockIdx.z;
    int m0 = blockIdx.y * 128, f0 = blockIdx.x * 128;
    const float* Bp = g_BT + (size_t)h * FF * KK;
    int warp_m = wid & 3, warp_n = wid >> 2;

    float acc[2][8][4];
#pragma unroll
    for (int a = 0; a < 2; a++)
#pragma unroll
        for (int bq = 0; bq < 8; bq++)
#pragma unroll
            for (int c = 0; c < 4; c++) acc[a][bq][c] = 0.f;

    int prow = tid & 127, pseg = tid >> 7;

    auto prod = [&](int c, int s) {
        float* As = sm + s * F_STG;
        float* Bs = As + F_AS;
        int k0 = c * 32;
        const float* asrc = g_A + (size_t)(m0 + prow) * KK + k0 + pseg * 16;
        const float* bsrc = Bp + (size_t)(f0 + prow) * KK + k0 + pseg * 16;
        uint32_t ad = smem_u32(As + prow * ST + pseg * 16);
        uint32_t bd = smem_u32(Bs + prow * ST + pseg * 16);
#pragma unroll
        for (int j = 0; j < 4; j++) {
            cpasync16(ad + j * 16, asrc + j * 4);
            cpasync16(bd + j * 16, bsrc + j * 4);
        }
    };
    auto domma = [&](int s) {
        float* As = sm + s * F_STG;
        float* Bs = As + F_AS;
#pragma unroll
        for (int ks = 0; ks < 4; ks++) {
            uint32_t a[2][4];
#pragma unroll
            for (int mt = 0; mt < 2; mt++) {
                int base = warp_m * 32 + mt * 16;
                a[mt][0] = __float_as_uint(As[(base + g) * ST + ks * 8 + tg]);
                a[mt][1] = __float_as_uint(As[(base + 8 + g) * ST + ks * 8 + tg]);
                a[mt][2] = __float_as_uint(As[(base + g) * ST + ks * 8 + tg + 4]);
                a[mt][3] = __float_as_uint(As[(base + 8 + g) * ST + ks * 8 + tg + 4]);
            }
#pragma unroll
            for (int nt = 0; nt < 8; nt++) {
                int fc = warp_n * 64 + nt * 8 + g;
                uint32_t b0 = __float_as_uint(Bs[fc * ST + ks * 8 + tg]);
                uint32_t b1 = __float_as_uint(Bs[fc * ST + ks * 8 + tg + 4]);
                mma1688(acc[0][nt], a[0], b0, b1);
                mma1688(acc[1][nt], a[1], b0, b1);
            }
        }
    };

    const int NIT = KK / 32;   // 32
    prod(0, 0); cp_commit();
    for (int i = 0; i < NIT; i++) {
        cp_wait<0>();
        __syncthreads();
        if (i + 1 < NIT) { prod(i + 1, (i + 1) & 1); cp_commit(); }
        domma(i & 1);
    }

    float* dst = g_featsT + (size_t)h * FF * NN;
#pragma unroll
    for (int mt = 0; mt < 2; mt++) {
#pragma unroll
        for (int nt = 0; nt < 8; nt++) {
            int row = m0 + warp_m * 32 + mt * 16 + g;
            int col = f0 + warp_n * 64 + nt * 8 + tg * 2;
            float b0v = g_bias2[h * FF + col];
            float b1v = g_bias2[h * FF + col + 1];
            dst[(size_t)col * NN + row]           = tf32r(acc[mt][nt][0] + b0v);
            dst[(size_t)(col + 1) * NN + row]     = tf32r(acc[mt][nt][1] + b1v);
            dst[(size_t)col * NN + row + 8]       = tf32r(acc[mt][nt][2] + b0v);
            dst[(size_t)(col + 1) * NN + row + 8] = tf32r(acc[mt][nt][3] + b1v);
        }
    }
}

// ================= fused attention GEMM (mma.sync tf32) =================
// CTA 128n x 128f, 512 threads (16 warps, 4 row-groups x 4 col-groups),
// warp tile 32n x 32f. Grid (4, 32) = 128 CTAs = one wave. 1 barrier/iter.
// w = 2^( s_n*t_m * (>=0 ? L2E : 0.3*L2E) + C_n ), C_n = log2(invz_n) - rmax_n*L2E
#define A_CONST 1024                // s_sm[512] + c_sm[512]
#define A_AS (128 * ST)             // 4608
#define A_STG (2 * A_AS)            // A + B = 9216
#define A_SMEM ((A_CONST + 2 * A_STG) * 4)   // 77824 bytes

__global__ __launch_bounds__(512) void attn_gemm(float* __restrict__ out) {
    extern __shared__ float sm[];
    float* s_sm = sm;              // [4h][128]
    float* c_sm = sm + 512;        // [4h][128]
    int tid = threadIdx.x, wid = tid >> 5, lane = tid & 31;
    int g = lane >> 2, tg = lane & 3;
    int n0 = blockIdx.y * 128, f0 = blockIdx.x * 128;
    int warp_m = wid & 3, warp_n = wid >> 2;

    {
        int hh = tid >> 7, nl = tid & 127;    // 512 = 4*128
        float iz = g_invz[hh * NN + n0 + nl];
        float rm = g_rmax[hh * NN + n0 + nl];
        s_sm[tid] = g_s[hh * NN + n0 + nl];
        c_sm[tid] = __log2f(iz) - rm * L2E;
    }

    float acc[2][4][4];
#pragma unroll
    for (int a = 0; a < 2; a++)
#pragma unroll
        for (int bq = 0; bq < 4; bq++)
#pragma unroll
            for (int c = 0; c < 4; c++) acc[a][bq][c] = 0.f;

    int nloc = tid & 127, kq = tid >> 7;      // weight gen: 8 k's each
    int prow = tid >> 2, pseg = tid & 3;      // B copy: 2 float4 each

    auto prod = [&](int c, int s) {
        float* As = sm + A_CONST + s * A_STG;
        float* Bs = As + A_AS;
        int h = c >> 7;
        int m0 = (c & 127) << 5;
        float sv = s_sm[h * 128 + nloc];
        float cn = c_sm[h * 128 + nloc];
        const float4* tp = (const float4*)(g_t + h * NN + m0 + kq * 8);
        float w[8];
#pragma unroll
        for (int q = 0; q < 2; q++) {
            float4 t4 = __ldg(tp + q);
            float tv[4] = {t4.x, t4.y, t4.z, t4.w};
#pragma unroll
            for (int r = 0; r < 4; r++) {
                float sc = sv * tv[r];
                float mult = sc >= 0.f ? L2E : (ALPHA * L2E);
                float y = fmaxf(fmaf(sc, mult, cn), -126.f);
                w[q * 4 + r] = tf32r(fex2(y));
            }
        }
        float* d = As + nloc * ST + kq * 8;
        *(float4*)d       = make_float4(w[0], w[1], w[2], w[3]);
        *(float4*)(d + 4) = make_float4(w[4], w[5], w[6], w[7]);
        const float* bsrc = g_featsT + (size_t)h * FF * NN
                          + (size_t)(f0 + prow) * NN + m0 + pseg * 8;
        uint32_t bd = smem_u32(Bs + prow * ST + pseg * 8);
        cpasync16(bd, bsrc);
        cpasync16(bd + 16, bsrc + 4);
    };
    auto domma = [&](int s) {
        float* As = sm + A_CONST + s * A_STG;
        float* Bs = As + A_AS;
#pragma unroll
        for (int ks = 0; ks < 4; ks++) {
            uint32_t a[2][4];
#pragma unroll
            for (int mt = 0; mt < 2; mt++) {
                int base = warp_m * 32 + mt * 16;
                a[mt][0] = __float_as_uint(As[(base + g) * ST + ks * 8 + tg]);
                a[mt][1] = __float_as_uint(As[(base + 8 + g) * ST + ks * 8 + tg]);
                a[mt][2] = __float_as_uint(As[(base + g) * ST + ks * 8 + tg + 4]);
                a[mt][3] = __float_as_uint(As[(base + 8 + g) * ST + ks * 8 + tg + 4]);
            }
#pragma unroll
            for (int nt = 0; nt < 4; nt++) {
                int fc = warp_n * 32 + nt * 8 + g;
                uint32_t b0 = __float_as_uint(Bs[fc * ST + ks * 8 + tg]);
                uint32_t b1 = __float_as_uint(Bs[fc * ST + ks * 8 + tg + 4]);
                mma1688(acc[0][nt], a[0], b0, b1);
                mma1688(acc[1][nt], a[1], b0, b1);
            }
        }
    };

    const int NIT = HH * (NN / 32);   // 512
    __syncthreads();                  // s_sm/c_sm ready
    prod(0, 0); cp_commit();
    for (int i = 0; i < NIT; i++) {
        cp_wait<0>();
        __syncthreads();
        if (i + 1 < NIT) { prod(i + 1, (i + 1) & 1); cp_commit(); }
        domma(i & 1);
    }

#pragma unroll
    for (int mt = 0; mt < 2; mt++) {
#pragma unroll
        for (int nt = 0; nt < 4; nt++) {
            int row = n0 + warp_m * 32 + mt * 16 + g;
            int col = f0 + warp_n * 32 + nt * 8 + tg * 2;
            float2 v0, v1;
            v0.x = fmaxf(0.25f * acc[mt][nt][0], 0.f);
            v0.y = fmaxf(0.25f * acc[mt][nt][1], 0.f);
            v1.x = fmaxf(0.25f * acc[mt][nt][2], 0.f);
            v1.y = fmaxf(0.25f * acc[mt][nt][3], 0.f);
            *(float2*)(out + (size_t)row * FF + col) = v0;
            *(float2*)(out + (size_t)(row + 8) * FF + col) = v1;
        }
    }
}

// ================= launch =================
extern "C" void kernel_launch(void* const* d_in, const int* in_sizes, int n_in,
                              void* d_out, int out_size)
{
    const float* nodes  = (const float*)d_in[0];
    const float* edges  = (const float*)d_in[1];
    const float* labels = (const float*)d_in[2];
    const float* We     = (const float*)d_in[3];
    const float* be     = (const float*)d_in[4];
    const float* Wm     = (const float*)d_in[5];
    const float* b      = (const float*)d_in[6];
    const float* u      = (const float*)d_in[7];
    const float* v      = (const float*)d_in[8];
    float* out = (float*)d_out;

    static bool attr_done = false;
    if (!attr_done) {
        cudaFuncSetAttribute(feats_gemm, cudaFuncAttributeMaxDynamicSharedMemorySize, F_SMEM);
        cudaFuncSetAttribute(attn_gemm, cudaFuncAttributeMaxDynamicSharedMemorySize, A_SMEM);
        cudaFuncSetAttribute(feats_gemm, cudaFuncAttributePreferredSharedMemoryCarveout, 100);
        cudaFuncSetAttribute(attn_gemm, cudaFuncAttributePreferredSharedMemoryCarveout, 100);
        attr_done = true;
    }

    setup_kernel<<<SETUP_BLOCKS, 256>>>(nodes, edges, labels, Wm, We, b, be, u, v);
    st_kernel<<<HH * NN / 8, 256>>>(nodes);
    minmax_kernel<<<HH, 256>>>();
    feats_gemm<<<dim3(FF / 128, NN / 128, HH), 256, F_SMEM>>>();  // capture slot 4
    z_kernel<<<HH * NN / 8, 256>>>();
    attn_gemm<<<dim3(FF / 128, NN / 128), 512, A_SMEM>>>(out);
}